// round 12
// baseline (speedup 1.0000x reference)
#include <cuda_runtime.h>

#define N_NODES 50000
#define N_EDGES 200000
#define OUTD 32
#define IN_SELF 128
#define EDGE_DIM 16

#define BN 128
#define KB 32
#define BNP 132
#define NT 256
#define SB 391                 // grid size == node tiles (exact mapping)

// Zero at module load; phase-2 restores zeros after consuming -> invariant
// holds across graph replays with no memset launch.
__device__ float g_scratch[N_NODES * OUTD + N_NODES];
__device__ unsigned g_barrier_ctr;   // monotonic, replay-safe

__device__ __forceinline__ void red_add_v4(float* ptr, float4 v) {
    asm volatile("red.global.add.v4.f32 [%0], {%1, %2, %3, %4};"
                 :: "l"(ptr), "f"(v.x), "f"(v.y), "f"(v.z), "f"(v.w)
                 : "memory");
}

__device__ __forceinline__ void fma2(unsigned long long& d,
                                     unsigned long long a,
                                     unsigned long long b) {
    asm("fma.rn.f32x2 %0, %1, %2, %0;" : "+l"(d) : "l"(a), "l"(b));
}

__device__ __forceinline__ unsigned long long packdup(float v) {
    unsigned long long r;
    asm("mov.b64 %0, {%1, %1};" : "=l"(r) : "f"(v));
    return r;
}

__device__ __forceinline__ void grid_barrier(unsigned G) {
    __syncthreads();
    if (threadIdx.x == 0) {
        __threadfence();
        unsigned old = atomicAdd(&g_barrier_ctr, 1u);
        unsigned target = (old / G + 1u) * G;
        unsigned cur;
        do {
            asm volatile("ld.global.acquire.gpu.u32 %0, [%1];"
                         : "=r"(cur) : "l"(&g_barrier_ctr));
            if (cur >= target) break;
            __nanosleep(32);
        } while (true);
    }
    __syncthreads();
}

// ---------------------------------------------------------------------------
// Fused kernel, grid = 391 (single wave by construction):
//   Phase 1: grid-strided edge scatter (R10's pipelined body).
//   Phase 2: node tile j = blockIdx.x (R7's split-K f32x2 GEMM),
//            bulk scratch self-clean after the epilogue.
// ---------------------------------------------------------------------------
__global__ void __launch_bounds__(NT, 3)
fused_kernel(const float* __restrict__ h_neigh,
             const float* __restrict__ h_self,
             const float* __restrict__ edge_features,
             const float* __restrict__ W_edge,
             const float* __restrict__ b_edge,
             const float* __restrict__ W_self,
             const float* __restrict__ W_neigh,
             const int* __restrict__ src,
             const int* __restrict__ dst,
             float* __restrict__ out) {
    __shared__ __align__(16) float pool[10624];   // 42.5KB union

    const unsigned G = gridDim.x;                 // 391
    const int t = threadIdx.x;

    float* g_agg = g_scratch;
    float* g_deg = g_scratch + N_NODES * OUTD;

    // ======================= PHASE 1: edge scatter =======================
    {
        float* sW = pool;           // [16][32]
        float* sb = pool + 512;     // [32]
        for (int idx = t; idx < OUTD * EDGE_DIM; idx += NT) {
            int j = idx >> 4, k = idx & 15;
            float s = 0.f;
            #pragma unroll
            for (int i = 0; i < OUTD; i++)
                s += W_edge[(i * OUTD + j) * EDGE_DIM + k];
            sW[k * OUTD + j] = s;
        }
        if (t < OUTD) {
            float s2 = 0.f;
            #pragma unroll
            for (int i = 0; i < OUTD; i++)
                s2 += b_edge[i * OUTD + t];
            sb[t] = s2;
        }
        __syncthreads();

        const int lane = t & 31;
        const int warp = t >> 5;
        const int g = lane >> 3;
        const int p = lane & 7;
        const int wpb = NT >> 5;                 // 8
        const int nwarps = (int)G * wpb;         // 3128
        const int NGROUPS = N_EDGES / 4;         // 50000

        const float4 biasv = *reinterpret_cast<const float4*>(&sb[4 * p]);

        int grp = blockIdx.x * wpb + warp;
        if (grp < NGROUPS) {
            int s = src[grp * 4 + g];
            int d = dst[grp * 4 + g];
            float2 ef = *reinterpret_cast<const float2*>(
                &edge_features[grp * 4 * EDGE_DIM + lane * 2]);

            #pragma unroll 1
            while (true) {
                float4 hv = *reinterpret_cast<const float4*>(
                    &h_neigh[s * OUTD + 4 * p]);

                int next = grp + nwarps;
                int s2 = 0, d2 = 0;
                float2 ef2 = make_float2(0.f, 0.f);
                bool more = (next < NGROUPS);
                if (more) {
                    s2 = src[next * 4 + g];
                    d2 = dst[next * 4 + g];
                    ef2 = *reinterpret_cast<const float2*>(
                        &edge_features[next * 4 * EDGE_DIM + lane * 2]);
                }

                float4 acc = biasv;
                #pragma unroll
                for (int k = 0; k < EDGE_DIM; k++) {
                    float ek = __shfl_sync(0xffffffffu, (k & 1) ? ef.y : ef.x, k >> 1, 8);
                    float4 w = *reinterpret_cast<const float4*>(&sW[k * OUTD + 4 * p]);
                    acc.x = fmaf(ek, w.x, acc.x);
                    acc.y = fmaf(ek, w.y, acc.y);
                    acc.z = fmaf(ek, w.z, acc.z);
                    acc.w = fmaf(ek, w.w, acc.w);
                }

                float4 msg = make_float4(hv.x * acc.x, hv.y * acc.y,
                                         hv.z * acc.z, hv.w * acc.w);
                red_add_v4(&g_agg[d * OUTD + 4 * p], msg);
                if (p == 0) atomicAdd(&g_deg[d], 1.0f);

                if (!more) break;
                s = s2; d = d2; ef = ef2; grp = next;
            }
        }
    }

    grid_barrier(G);   // all REDs visible; smem free for reuse

    // ======================= PHASE 2: node GEMM =======================
    {
        float (*h_s)[KB][BNP] = reinterpret_cast<float(*)[KB][BNP]>(pool);          // 8448
        float (*w_s)[KB][OUTD] = reinterpret_cast<float(*)[KB][OUTD]>(pool + 8448); // 2048
        float* sinv = pool + 10496;                                                  // 128

        const int nbase = blockIdx.x * BN;
        const int kg = t >> 7;
        const int t1 = t & 127;
        const int tn = t1 >> 3;
        const int tc = t1 & 7;
        const int ko = kg * (KB / 2);

        const int snode = t >> 3;
        const int skvec = t & 7;
        const int wchan = t >> 3;
        const int wkvec = t & 7;

        if (t < BN) {
            int gn = nbase + t;
            if (gn < N_NODES) {
                float dv = g_deg[gn];
                g_deg[gn] = 0.f;                  // self-clean deg (cheap)
                sinv[t] = 1.0f / fmaxf(dv, 1.0f);
            } else {
                sinv[t] = 0.f;
            }
        }

        float4 hreg[4];
        float4 wreg;

        auto load_regs = [&](int kc) {
            #pragma unroll
            for (int i = 0; i < 4; i++) {
                int node = snode + i * (NT >> 3);
                int gn = nbase + node;
                float4 v = make_float4(0.f, 0.f, 0.f, 0.f);
                if (gn < N_NODES) {
                    if (kc < 4) {
                        v = *reinterpret_cast<const float4*>(
                            &h_self[gn * IN_SELF + kc * KB + skvec * 4]);
                    } else {
                        v = *reinterpret_cast<const float4*>(
                            &g_agg[gn * OUTD + skvec * 4]);
                        float iv = sinv[node];
                        v.x *= iv; v.y *= iv; v.z *= iv; v.w *= iv;
                    }
                }
                hreg[i] = v;
            }
            if (kc < 4)
                wreg = *reinterpret_cast<const float4*>(
                    &W_self[wchan * IN_SELF + kc * KB + wkvec * 4]);
            else
                wreg = *reinterpret_cast<const float4*>(
                    &W_neigh[wchan * OUTD + wkvec * 4]);
        };

        auto store_smem = [&](int b) {
            #pragma unroll
            for (int i = 0; i < 4; i++) {
                int node = snode + i * (NT >> 3);
                h_s[b][skvec * 4 + 0][node] = hreg[i].x;
                h_s[b][skvec * 4 + 1][node] = hreg[i].y;
                h_s[b][skvec * 4 + 2][node] = hreg[i].z;
                h_s[b][skvec * 4 + 3][node] = hreg[i].w;
            }
            w_s[b][wkvec * 4 + 0][wchan] = wreg.x;
            w_s[b][wkvec * 4 + 1][wchan] = wreg.y;
            w_s[b][wkvec * 4 + 2][wchan] = wreg.z;
            w_s[b][wkvec * 4 + 3][wchan] = wreg.w;
        };

        unsigned long long acc2[4][4];
        #pragma unroll
        for (int p = 0; p < 4; p++)
            #pragma unroll
            for (int c = 0; c < 4; c++) acc2[p][c] = 0ull;

        load_regs(0);
        __syncthreads();      // sinv visible
        store_smem(0);
        __syncthreads();

        #pragma unroll
        for (int kc = 0; kc < 5; kc++) {
            int b = kc & 1;
            if (kc < 4) load_regs(kc + 1);
            #pragma unroll
            for (int kk = 0; kk < KB / 2; kk++) {
                int k = kk + ko;
                float4 w = *reinterpret_cast<const float4*>(&w_s[b][k][tc * 4]);
                unsigned long long w0 = packdup(w.x);
                unsigned long long w1 = packdup(w.y);
                unsigned long long w2 = packdup(w.z);
                unsigned long long w3 = packdup(w.w);
                ulonglong2 hA = *reinterpret_cast<const ulonglong2*>(&h_s[b][k][tn * 8]);
                ulonglong2 hB = *reinterpret_cast<const ulonglong2*>(&h_s[b][k][tn * 8 + 4]);

                fma2(acc2[0][0], hA.x, w0);
                fma2(acc2[0][1], hA.x, w1);
                fma2(acc2[0][2], hA.x, w2);
                fma2(acc2[0][3], hA.x, w3);
                fma2(acc2[1][0], hA.y, w0);
                fma2(acc2[1][1], hA.y, w1);
                fma2(acc2[1][2], hA.y, w2);
                fma2(acc2[1][3], hA.y, w3);
                fma2(acc2[2][0], hB.x, w0);
                fma2(acc2[2][1], hB.x, w1);
                fma2(acc2[2][2], hB.x, w2);
                fma2(acc2[2][3], hB.x, w3);
                fma2(acc2[3][0], hB.y, w0);
                fma2(acc2[3][1], hB.y, w1);
                fma2(acc2[3][2], hB.y, w2);
                fma2(acc2[3][3], hB.y, w3);
            }
            if (kc < 4) store_smem(1 - b);
            __syncthreads();
        }

        unsigned long long* red = reinterpret_cast<unsigned long long*>(pool);
        if (kg == 1) {
            #pragma unroll
            for (int p = 0; p < 4; p++)
                #pragma unroll
                for (int c = 0; c < 4; c++)
                    red[t1 * 16 + p * 4 + c] = acc2[p][c];
        }
        __syncthreads();
        if (kg == 0) {
            #pragma unroll
            for (int p = 0; p < 4; p++) {
                float lo[4], hi[4];
                #pragma unroll
                for (int c = 0; c < 4; c++) {
                    float2 a = *reinterpret_cast<float2*>(&acc2[p][c]);
                    unsigned long long o = red[t1 * 16 + p * 4 + c];
                    float2 bq = *reinterpret_cast<float2*>(&o);
                    lo[c] = fmaxf(a.x + bq.x, 0.f);
                    hi[c] = fmaxf(a.y + bq.y, 0.f);
                }
                int gn0 = nbase + tn * 8 + 2 * p;
                if (gn0 < N_NODES)
                    *reinterpret_cast<float4*>(&out[gn0 * OUTD + tc * 4]) =
                        make_float4(lo[0], lo[1], lo[2], lo[3]);
                if (gn0 + 1 < N_NODES)
                    *reinterpret_cast<float4*>(&out[(gn0 + 1) * OUTD + tc * 4]) =
                        make_float4(hi[0], hi[1], hi[2], hi[3]);
            }
        }

        // ---- bulk self-clean of this block's agg slice (off critical path) ----
        {
            const int nvalid = min(BN, N_NODES - nbase);        // nodes in tile
            const int nq = nvalid * (OUTD / 4);                 // float4 count
            float4* ap = reinterpret_cast<float4*>(&g_agg[nbase * OUTD]);
            const float4 z = make_float4(0.f, 0.f, 0.f, 0.f);
            for (int i = t; i < nq; i += NT)
                ap[i] = z;
        }
    }
}

extern "C" void kernel_launch(void* const* d_in, const int* in_sizes, int n_in,
                              void* d_out, int out_size) {
    const float* h_neigh       = (const float*)d_in[0];
    const float* h_self        = (const float*)d_in[1];
    const float* edge_features = (const float*)d_in[2];
    const float* W_edge        = (const float*)d_in[3];
    const float* b_edge        = (const float*)d_in[4];
    const float* W_self        = (const float*)d_in[5];
    const float* W_neigh       = (const float*)d_in[6];
    const int*   src           = (const int*)d_in[7];
    const int*   dst           = (const int*)d_in[8];
    float* out = (float*)d_out;

    // Single launch. Grid 391 = one block per node tile; co-resident in one
    // wave (148 SMs x 3 blocks = 444 slots), so the grid barrier is safe.
    fused_kernel<<<SB, NT>>>(h_neigh, h_self, edge_features,
                             W_edge, b_edge, W_self, W_neigh,
                             src, dst, out);
}

// round 13
// speedup vs baseline: 1.0963x; 1.0963x over previous
#include <cuda_runtime.h>

#define N_NODES 50000
#define N_EDGES 200000
#define OUTD 32
#define IN_SELF 128
#define EDGE_DIM 16

#define EDGE_BLOCKS 592
#define EDGE_THREADS 256

#define BN 128
#define KB 32
#define BNP 132
#define NT 256
#define SB 391

// Zero-initialized at module load; node_kernel restores zeros AFTER its
// epilogue (bulk, off the critical path), so the zero-invariant holds
// across graph replays with no memset launch.
__device__ float g_scratch[N_NODES * OUTD + N_NODES];

__device__ __forceinline__ void red_add_v4(float* ptr, float4 v) {
    asm volatile("red.global.add.v4.f32 [%0], {%1, %2, %3, %4};"
                 :: "l"(ptr), "f"(v.x), "f"(v.y), "f"(v.z), "f"(v.w)
                 : "memory");
}

__device__ __forceinline__ void fma2(unsigned long long& d,
                                     unsigned long long a,
                                     unsigned long long b) {
    asm("fma.rn.f32x2 %0, %1, %2, %0;" : "+l"(d) : "l"(a), "l"(b));
}

__device__ __forceinline__ unsigned long long packdup(float v) {
    unsigned long long r;
    asm("mov.b64 %0, {%1, %1};" : "=l"(r) : "f"(v));
    return r;
}

// ---------------------------------------------------------------------------
// Edge kernel (R10 verbatim, proven): software-pipelined scatter.
// ---------------------------------------------------------------------------
__global__ void __launch_bounds__(EDGE_THREADS)
edge_kernel(const float* __restrict__ h_neigh,
            const float* __restrict__ edge_features,
            const float* __restrict__ W_edge,
            const float* __restrict__ b_edge,
            const int* __restrict__ src,
            const int* __restrict__ dst) {
    __shared__ __align__(16) float sW[EDGE_DIM * OUTD];
    __shared__ __align__(16) float sb[OUTD];
    {
        for (int idx = threadIdx.x; idx < OUTD * EDGE_DIM; idx += EDGE_THREADS) {
            int j = idx >> 4, k = idx & 15;
            float s = 0.f;
            #pragma unroll
            for (int i = 0; i < OUTD; i++)
                s += W_edge[(i * OUTD + j) * EDGE_DIM + k];
            sW[k * OUTD + j] = s;
        }
        if (threadIdx.x < OUTD) {
            float s2 = 0.f;
            #pragma unroll
            for (int i = 0; i < OUTD; i++)
                s2 += b_edge[i * OUTD + threadIdx.x];
            sb[threadIdx.x] = s2;
        }
    }
    __syncthreads();

    float* g_agg = g_scratch;
    float* g_deg = g_scratch + N_NODES * OUTD;

    const int lane = threadIdx.x & 31;
    const int warp = threadIdx.x >> 5;
    const int g = lane >> 3;
    const int p = lane & 7;
    const int wpb = EDGE_THREADS >> 5;
    const int nwarps = EDGE_BLOCKS * wpb;       // 4736
    const int NGROUPS = N_EDGES / 4;            // 50000

    const float4 biasv = *reinterpret_cast<const float4*>(&sb[4 * p]);

    int grp = blockIdx.x * wpb + warp;
    if (grp >= NGROUPS) return;

    int s = src[grp * 4 + g];
    int d = dst[grp * 4 + g];
    float2 ef = *reinterpret_cast<const float2*>(
        &edge_features[grp * 4 * EDGE_DIM + lane * 2]);

    #pragma unroll 1
    while (true) {
        float4 hv = *reinterpret_cast<const float4*>(&h_neigh[s * OUTD + 4 * p]);

        int next = grp + nwarps;
        int s2 = 0, d2 = 0;
        float2 ef2 = make_float2(0.f, 0.f);
        bool more = (next < NGROUPS);
        if (more) {
            s2 = src[next * 4 + g];
            d2 = dst[next * 4 + g];
            ef2 = *reinterpret_cast<const float2*>(
                &edge_features[next * 4 * EDGE_DIM + lane * 2]);
        }

        float4 acc = biasv;
        #pragma unroll
        for (int k = 0; k < EDGE_DIM; k++) {
            float ek = __shfl_sync(0xffffffffu, (k & 1) ? ef.y : ef.x, k >> 1, 8);
            float4 w = *reinterpret_cast<const float4*>(&sW[k * OUTD + 4 * p]);
            acc.x = fmaf(ek, w.x, acc.x);
            acc.y = fmaf(ek, w.y, acc.y);
            acc.z = fmaf(ek, w.z, acc.z);
            acc.w = fmaf(ek, w.w, acc.w);
        }

        float4 msg = make_float4(hv.x * acc.x, hv.y * acc.y,
                                 hv.z * acc.z, hv.w * acc.w);
        red_add_v4(&g_agg[d * OUTD + 4 * p], msg);
        if (p == 0) atomicAdd(&g_deg[d], 1.0f);

        if (!more) break;
        s = s2; d = d2; ef = ef2; grp = next;
    }
}

// ---------------------------------------------------------------------------
// Node kernel: R10's clean split-K f32x2 GEMM body (proven 24.2us) +
//   deg self-clean in the sinv setup (1 store/128 thr, free)
//   agg self-clean as a BULK loop after the epilogue (off critical path)
// ---------------------------------------------------------------------------
__global__ void __launch_bounds__(NT, 3)
node_kernel(const float* __restrict__ h_self,
            const float* __restrict__ W_self,
            const float* __restrict__ W_neigh,
            float* __restrict__ out) {
    __shared__ __align__(16) float h_s[2][KB][BNP];
    __shared__ __align__(16) float w_s[2][KB][OUTD];
    __shared__ float sinv[BN];

    float* g_agg = g_scratch;
    float* g_deg = g_scratch + N_NODES * OUTD;

    const int t = threadIdx.x;
    const int nbase = blockIdx.x * BN;
    const int kg = t >> 7;
    const int t1 = t & 127;
    const int tn = t1 >> 3;
    const int tc = t1 & 7;
    const int ko = kg * (KB / 2);

    const int snode = t >> 3;
    const int skvec = t & 7;
    const int wchan = t >> 3;
    const int wkvec = t & 7;

    if (t < BN) {
        int gn = nbase + t;
        if (gn < N_NODES) {
            float dv = g_deg[gn];
            g_deg[gn] = 0.f;                     // self-clean deg (cheap)
            sinv[t] = 1.0f / fmaxf(dv, 1.0f);
        } else {
            sinv[t] = 0.f;
        }
    }

    float4 hreg[4];
    float4 wreg;

    auto load_regs = [&](int kc) {
        #pragma unroll
        for (int i = 0; i < 4; i++) {
            int node = snode + i * (NT >> 3);
            int gn = nbase + node;
            float4 v = make_float4(0.f, 0.f, 0.f, 0.f);
            if (gn < N_NODES) {
                if (kc < 4) {
                    v = *reinterpret_cast<const float4*>(
                        &h_self[gn * IN_SELF + kc * KB + skvec * 4]);
                } else {
                    v = *reinterpret_cast<const float4*>(
                        &g_agg[gn * OUTD + skvec * 4]);
                    float iv = sinv[node];
                    v.x *= iv; v.y *= iv; v.z *= iv; v.w *= iv;
                }
            }
            hreg[i] = v;
        }
        if (kc < 4)
            wreg = *reinterpret_cast<const float4*>(
                &W_self[wchan * IN_SELF + kc * KB + wkvec * 4]);
        else
            wreg = *reinterpret_cast<const float4*>(
                &W_neigh[wchan * OUTD + wkvec * 4]);
    };

    auto store_smem = [&](int b) {
        #pragma unroll
        for (int i = 0; i < 4; i++) {
            int node = snode + i * (NT >> 3);
            h_s[b][skvec * 4 + 0][node] = hreg[i].x;
            h_s[b][skvec * 4 + 1][node] = hreg[i].y;
            h_s[b][skvec * 4 + 2][node] = hreg[i].z;
            h_s[b][skvec * 4 + 3][node] = hreg[i].w;
        }
        w_s[b][wkvec * 4 + 0][wchan] = wreg.x;
        w_s[b][wkvec * 4 + 1][wchan] = wreg.y;
        w_s[b][wkvec * 4 + 2][wchan] = wreg.z;
        w_s[b][wkvec * 4 + 3][wchan] = wreg.w;
    };

    unsigned long long acc2[4][4];
    #pragma unroll
    for (int p = 0; p < 4; p++)
        #pragma unroll
        for (int c = 0; c < 4; c++) acc2[p][c] = 0ull;

    load_regs(0);
    __syncthreads();      // sinv visible, smem free
    store_smem(0);
    __syncthreads();

    #pragma unroll
    for (int kc = 0; kc < 5; kc++) {
        int b = kc & 1;
        if (kc < 4) load_regs(kc + 1);
        #pragma unroll
        for (int kk = 0; kk < KB / 2; kk++) {
            int k = kk + ko;
            float4 w = *reinterpret_cast<const float4*>(&w_s[b][k][tc * 4]);
            unsigned long long w0 = packdup(w.x);
            unsigned long long w1 = packdup(w.y);
            unsigned long long w2 = packdup(w.z);
            unsigned long long w3 = packdup(w.w);
            ulonglong2 hA = *reinterpret_cast<const ulonglong2*>(&h_s[b][k][tn * 8]);
            ulonglong2 hB = *reinterpret_cast<const ulonglong2*>(&h_s[b][k][tn * 8 + 4]);

            fma2(acc2[0][0], hA.x, w0);
            fma2(acc2[0][1], hA.x, w1);
            fma2(acc2[0][2], hA.x, w2);
            fma2(acc2[0][3], hA.x, w3);
            fma2(acc2[1][0], hA.y, w0);
            fma2(acc2[1][1], hA.y, w1);
            fma2(acc2[1][2], hA.y, w2);
            fma2(acc2[1][3], hA.y, w3);
            fma2(acc2[2][0], hB.x, w0);
            fma2(acc2[2][1], hB.x, w1);
            fma2(acc2[2][2], hB.x, w2);
            fma2(acc2[2][3], hB.x, w3);
            fma2(acc2[3][0], hB.y, w0);
            fma2(acc2[3][1], hB.y, w1);
            fma2(acc2[3][2], hB.y, w2);
            fma2(acc2[3][3], hB.y, w3);
        }
        if (kc < 4) store_smem(1 - b);
        __syncthreads();
    }

    unsigned long long* red = reinterpret_cast<unsigned long long*>(h_s);
    if (kg == 1) {
        #pragma unroll
        for (int p = 0; p < 4; p++)
            #pragma unroll
            for (int c = 0; c < 4; c++)
                red[t1 * 16 + p * 4 + c] = acc2[p][c];
    }
    __syncthreads();
    if (kg == 0) {
        #pragma unroll
        for (int p = 0; p < 4; p++) {
            float lo[4], hi[4];
            #pragma unroll
            for (int c = 0; c < 4; c++) {
                float2 a = *reinterpret_cast<float2*>(&acc2[p][c]);
                unsigned long long o = red[t1 * 16 + p * 4 + c];
                float2 bq = *reinterpret_cast<float2*>(&o);
                lo[c] = fmaxf(a.x + bq.x, 0.f);
                hi[c] = fmaxf(a.y + bq.y, 0.f);
            }
            int gn0 = nbase + tn * 8 + 2 * p;
            if (gn0 < N_NODES)
                *reinterpret_cast<float4*>(&out[gn0 * OUTD + tc * 4]) =
                    make_float4(lo[0], lo[1], lo[2], lo[3]);
            if (gn0 + 1 < N_NODES)
                *reinterpret_cast<float4*>(&out[(gn0 + 1) * OUTD + tc * 4]) =
                    make_float4(hi[0], hi[1], hi[2], hi[3]);
        }
    }

    // ---- bulk self-clean of this block's agg slice (off critical path) ----
    {
        const int nvalid = min(BN, N_NODES - nbase);
        const int nq = nvalid * (OUTD / 4);
        float4* ap = reinterpret_cast<float4*>(&g_agg[nbase * OUTD]);
        const float4 z = make_float4(0.f, 0.f, 0.f, 0.f);
        for (int i = t; i < nq; i += NT)
            ap[i] = z;
    }
}

extern "C" void kernel_launch(void* const* d_in, const int* in_sizes, int n_in,
                              void* d_out, int out_size) {
    const float* h_neigh       = (const float*)d_in[0];
    const float* h_self        = (const float*)d_in[1];
    const float* edge_features = (const float*)d_in[2];
    const float* W_edge        = (const float*)d_in[3];
    const float* b_edge        = (const float*)d_in[4];
    const float* W_self        = (const float*)d_in[5];
    const float* W_neigh       = (const float*)d_in[6];
    const int*   src           = (const int*)d_in[7];
    const int*   dst           = (const int*)d_in[8];
    float* out = (float*)d_out;

    // Two launches, no memset: scratch zeroed at load, node_kernel restores
    // zeros post-epilogue each run (replay-safe).
    edge_kernel<<<EDGE_BLOCKS, EDGE_THREADS>>>(h_neigh, edge_features,
                                               W_edge, b_edge, src, dst);
    node_kernel<<<SB, NT>>>(h_self, W_self, W_neigh, out);
}